// round 15
// baseline (speedup 1.0000x reference)
#include <cuda_runtime.h>
#include <cuda_fp16.h>
#include <cstdint>

// ---------------- problem dims ----------------
#define BS    4
#define SEQ   4096
#define DIN   1024
#define HDIM  1024
#define M_TOTAL (BS*SEQ)       // 16384
#define NCHUNK 64
#define CHUNK  (SEQ/NCHUNK)    // 64

// ---------------- GEMM tiling ----------------
#define BM 128
#define BN 128
#define BK 64
#define KTILES (DIN/BK)        // 16
#define STAGES 4

#define TILE_BYTES (128*128)
#define STAGE_BYTES (3*TILE_BYTES)         // 48 KB
#define DYN_SMEM (STAGES*STAGE_BYTES)      // 192 KB

// ---------------- scratch ----------------
__device__ uint32_t g_AB[(size_t)M_TOTAL*HDIM]; // packed half2 (a, b)
__device__ float g_AggA[BS*NCHUNK*HDIM];
__device__ float g_AggB[BS*NCHUNK*HDIM];
__device__ float g_Carry[BS*NCHUNK*HDIM];
__device__ __half g_x16[(size_t)M_TOTAL*DIN];
__device__ __half g_wz16[HDIM*DIN];
__device__ __half g_wh16[HDIM*DIN];

// ---------------- helpers ----------------
__device__ __forceinline__ uint32_t smem_u32(const void* p) {
    uint32_t a;
    asm("{ .reg .u64 t; cvta.to.shared.u64 t, %1; cvt.u32.u64 %0, t; }"
        : "=r"(a) : "l"(p));
    return a;
}

__device__ __forceinline__ void cp_async16(uint32_t saddr, const void* gptr) {
    asm volatile("cp.async.cg.shared.global [%0], [%1], 16;"
                 :: "r"(saddr), "l"(gptr) : "memory");
}
#define CP_COMMIT() asm volatile("cp.async.commit_group;" ::: "memory")
#define CP_WAIT2()  asm volatile("cp.async.wait_group 2;" ::: "memory")

__device__ __forceinline__ void ldmatrix_x4(uint32_t* r, uint32_t addr) {
    asm volatile("ldmatrix.sync.aligned.m8n8.x4.shared.b16 {%0,%1,%2,%3}, [%4];"
                 : "=r"(r[0]), "=r"(r[1]), "=r"(r[2]), "=r"(r[3]) : "r"(addr));
}

__device__ __forceinline__ void mma_fp16(float* d, const uint32_t* a,
                                         uint32_t b0, uint32_t b1) {
    asm volatile(
        "mma.sync.aligned.m16n8k16.row.col.f32.f16.f16.f32 "
        "{%0,%1,%2,%3}, {%4,%5,%6,%7}, {%8,%9}, {%0,%1,%2,%3};"
        : "+f"(d[0]), "+f"(d[1]), "+f"(d[2]), "+f"(d[3])
        : "r"(a[0]), "r"(a[1]), "r"(a[2]), "r"(a[3]), "r"(b0), "r"(b1));
}

__device__ __forceinline__ float g_fn(float x) {
    return (x >= 0.0f) ? (x + 0.5f) : 1.0f / (1.0f + __expf(-x));
}

__device__ __forceinline__ uint32_t pack_ab(float a, float b) {
    __half2 h = __floats2half2_rn(a, b);
    return *(uint32_t*)&h;
}
__device__ __forceinline__ void unpack_ab(uint32_t u, float& a, float& b) {
    __half2 h = *(__half2*)&u;
    a = __low2float(h);
    b = __high2float(h);
}

// ---------------- fp32 -> fp16 convert (8 floats / thread) ----------------
#define CVT_X8  (M_TOTAL*DIN/8)
#define CVT_W8  (HDIM*DIN/8)
__global__ void convert_kernel(const float* __restrict__ x,
                               const float* __restrict__ Wz,
                               const float* __restrict__ Wh)
{
    const int i = blockIdx.x * blockDim.x + threadIdx.x;
    const float* src; __half* dst; int j;
    if (i < CVT_X8)                { src = x;  dst = g_x16;  j = i; }
    else if (i < CVT_X8 + CVT_W8)  { src = Wz; dst = g_wz16; j = i - CVT_X8; }
    else                           { src = Wh; dst = g_wh16; j = i - CVT_X8 - CVT_W8; }
    const float4* s = (const float4*)(src + (size_t)j * 8);
    float4 v0 = s[0], v1 = s[1];
    __half2 h0 = __floats2half2_rn(v0.x, v0.y);
    __half2 h1 = __floats2half2_rn(v0.z, v0.w);
    __half2 h2 = __floats2half2_rn(v1.x, v1.y);
    __half2 h3 = __floats2half2_rn(v1.z, v1.w);
    uint4 pk = make_uint4(*(uint32_t*)&h0, *(uint32_t*)&h1,
                          *(uint32_t*)&h2, *(uint32_t*)&h3);
    *(uint4*)(dst + (size_t)j * 8) = pk;
}

// ---------------- fused dual GEMM (fp16 mma) + gate epilogue ----------------
__global__ void __launch_bounds__(256, 1)
gemm_gate_kernel(const float* __restrict__ bz, const float* __restrict__ bh)
{
    extern __shared__ __align__(16) char dyn_smem[];
    __shared__ float sbz[BN], sbh[BN];

    const uint32_t dynb = smem_u32(dyn_smem);
    const int tid  = threadIdx.x;
    const int warp = tid >> 5;
    const int lane = tid & 31;
    const int n0 = blockIdx.x * BN;
    const int m0 = blockIdx.y * BM;

    const int wm = warp >> 2;
    const int wn = warp & 3;

    if (tid < BN) { sbz[tid] = bz[n0 + tid]; sbh[tid] = bh[n0 + tid]; }

    uint32_t stA[STAGES], stBz[STAGES], stBh[STAGES];
#pragma unroll
    for (int s = 0; s < STAGES; s++) {
        stA[s]  = dynb + s * STAGE_BYTES;
        stBz[s] = stA[s] + TILE_BYTES;
        stBh[s] = stBz[s] + TILE_BYTES;
    }

    auto load_stage = [&](int kt, int s) {
        const int kb = kt * BK;
#pragma unroll
        for (int i = 0; i < 4; i++) {
            int v = tid + i * 256, r = v >> 3, c = v & 7;
            uint32_t off = (uint32_t)(r * 128 + ((c ^ (r & 7)) << 4));
            cp_async16(stA[s] + off,  g_x16  + (size_t)(m0 + r) * DIN + kb + c * 8);
            cp_async16(stBz[s] + off, g_wz16 + (size_t)(n0 + r) * DIN + kb + c * 8);
            cp_async16(stBh[s] + off, g_wh16 + (size_t)(n0 + r) * DIN + kb + c * 8);
        }
    };

    float acc[2][4][4][4];
#pragma unroll
    for (int o = 0; o < 2; o++)
#pragma unroll
        for (int a = 0; a < 4; a++)
#pragma unroll
            for (int b = 0; b < 4; b++)
#pragma unroll
                for (int c = 0; c < 4; c++) acc[o][a][b][c] = 0.f;

    load_stage(0, 0); CP_COMMIT();
    load_stage(1, 1); CP_COMMIT();
    load_stage(2, 2); CP_COMMIT();

    const int lrow = lane & 15;
    const int lkh  = lane >> 4;

    uint32_t afrag[2][4][4];
    uint32_t bfZ[2][2][4];
    uint32_t bfH[2][2][4];

    for (int kt = 0; kt < KTILES; kt++) {
        CP_WAIT2();
        __syncthreads();
        if (kt + 3 < KTILES) load_stage(kt + 3, (kt + 3) % STAGES);
        CP_COMMIT();

        const int s = kt % STAGES;
        const uint32_t baseA = stA[s], baseZ = stBz[s], baseH = stBh[s];

        auto frag_load = [&](int ks, int buf) {
            const int ch = ks * 2 + lkh;
#pragma unroll
            for (int mf = 0; mf < 4; mf++) {
                const int row = wm * 64 + mf * 16 + lrow;
                ldmatrix_x4(afrag[buf][mf], baseA + row * 128 + ((ch ^ (row & 7)) << 4));
            }
#pragma unroll
            for (int g = 0; g < 2; g++) {
                const int row = wn * 32 + g * 16 + lrow;
                const uint32_t soff = row * 128 + ((ch ^ (row & 7)) << 4);
                ldmatrix_x4(bfZ[buf][g], baseZ + soff);
                ldmatrix_x4(bfH[buf][g], baseH + soff);
            }
        };

        frag_load(0, 0);
#pragma unroll
        for (int ks = 0; ks < 4; ks++) {
            const int cur = ks & 1;
            if (ks < 3) frag_load(ks + 1, cur ^ 1);
#pragma unroll
            for (int g = 0; g < 2; g++) {
#pragma unroll
                for (int mf = 0; mf < 4; mf++) {
                    mma_fp16(acc[0][mf][g * 2 + 0], afrag[cur][mf], bfZ[cur][g][0], bfZ[cur][g][2]);
                    mma_fp16(acc[0][mf][g * 2 + 1], afrag[cur][mf], bfZ[cur][g][1], bfZ[cur][g][3]);
                    mma_fp16(acc[1][mf][g * 2 + 0], afrag[cur][mf], bfH[cur][g][0], bfH[cur][g][2]);
                    mma_fp16(acc[1][mf][g * 2 + 1], afrag[cur][mf], bfH[cur][g][1], bfH[cur][g][3]);
                }
            }
        }
    }
    __syncthreads();

    // ---------- epilogue: gates + store packed (a,b) ----------
#pragma unroll
    for (int mf = 0; mf < 4; mf++) {
#pragma unroll
        for (int nf = 0; nf < 4; nf++) {
            const int nl = wn * 32 + nf * 8 + (lane & 3) * 2;
            const float bz0 = sbz[nl], bz1 = sbz[nl + 1];
            const float bh0 = sbh[nl], bh1 = sbh[nl + 1];
#pragma unroll
            for (int rr = 0; rr < 2; rr++) {
                const int m = m0 + wm * 64 + mf * 16 + (lane >> 2) + rr * 8;
                const float k0 = acc[0][mf][nf][rr * 2 + 0] + bz0;
                const float k1 = acc[0][mf][nf][rr * 2 + 1] + bz1;
                const float p0 = acc[1][mf][nf][rr * 2 + 0] + bh0;
                const float p1 = acc[1][mf][nf][rr * 2 + 1] + bh1;
                const float a0 = 1.0f / (1.0f + __expf(k0));
                const float a1 = 1.0f / (1.0f + __expf(k1));
                const float b0 = (1.0f - a0) * g_fn(p0);
                const float b1 = (1.0f - a1) * g_fn(p1);
                *(uint2*)&g_AB[(size_t)m * HDIM + n0 + nl] =
                    make_uint2(pack_ab(a0, b0), pack_ab(a1, b1));
            }
        }
    }
}

// ---------------- scan pass 1: per-chunk aggregates (4 channels/thread) ----------------
__global__ void scan_agg_kernel()
{
    const int h4 = blockIdx.x * blockDim.x + threadIdx.x;   // channel quad
    const int c = blockIdx.y;
    const int b = blockIdx.z;
    const uint4* src = (const uint4*)g_AB
                     + (size_t)(b * SEQ + c * CHUNK) * (HDIM / 4) + h4;

    float A0 = 1.f, B0 = 0.f, A1 = 1.f, B1 = 0.f;
    float A2 = 1.f, B2 = 0.f, A3 = 1.f, B3 = 0.f;
#pragma unroll 8
    for (int s = 0; s < CHUNK; s++) {
        uint4 u = src[(size_t)s * (HDIM / 4)];
        float a0, b0, a1, b1, a2, b2, a3, b3;
        unpack_ab(u.x, a0, b0); unpack_ab(u.y, a1, b1);
        unpack_ab(u.z, a2, b2); unpack_ab(u.w, a3, b3);
        B0 = fmaf(a0, B0, b0); A0 *= a0;
        B1 = fmaf(a1, B1, b1); A1 *= a1;
        B2 = fmaf(a2, B2, b2); A2 *= a2;
        B3 = fmaf(a3, B3, b3); A3 *= a3;
    }
    const int o = (b * NCHUNK + c) * HDIM + 4 * h4;
    *(float4*)&g_AggA[o] = make_float4(A0, A1, A2, A3);
    *(float4*)&g_AggB[o] = make_float4(B0, B1, B2, B3);
}

// ---------------- scan pass 2: inter-chunk carry (64 CTAs x 64 thr) ----------------
__global__ void scan_carry_kernel(const float* __restrict__ h0in)
{
    const int h = blockIdx.x * blockDim.x + threadIdx.x;
    const int b = blockIdx.y;
    float carry = g_fn(h0in[b * HDIM + h]);

    const int base = b * NCHUNK * HDIM + h;

    float A[2][16], Bv[2][16];
#pragma unroll
    for (int j = 0; j < 16; j++) {
        A[0][j]  = g_AggA[base + j * HDIM];
        Bv[0][j] = g_AggB[base + j * HDIM];
    }

#pragma unroll
    for (int grp = 0; grp < 4; grp++) {
        const int cb = grp & 1;
        if (grp < 3) {
            const int nb = base + (grp + 1) * 16 * HDIM;
#pragma unroll
            for (int j = 0; j < 16; j++) {
                A[cb ^ 1][j]  = g_AggA[nb + j * HDIM];
                Bv[cb ^ 1][j] = g_AggB[nb + j * HDIM];
            }
        }
        const int ob = base + grp * 16 * HDIM;
#pragma unroll
        for (int j = 0; j < 16; j++) {
            g_Carry[ob + j * HDIM] = carry;
            carry = fmaf(A[cb][j], carry, Bv[cb][j]);
        }
    }
}

// ---------------- scan pass 3: apply + write output (4 channels/thread) ----------------
__global__ void scan_apply_kernel(float* __restrict__ out)
{
    const int h4 = blockIdx.x * blockDim.x + threadIdx.x;   // channel quad
    const int c = blockIdx.y;
    const int b = blockIdx.z;
    const uint4* src = (const uint4*)g_AB
                     + (size_t)(b * SEQ + c * CHUNK) * (HDIM / 4) + h4;
    float4* dst = (float4*)(out + (size_t)(b * SEQ + c * CHUNK) * HDIM) + h4;

    const int co = (b * NCHUNK + c) * HDIM + 4 * h4;
    float4 hc = *(const float4*)&g_Carry[co];
    float h0 = hc.x, h1 = hc.y, h2 = hc.z, h3 = hc.w;
#pragma unroll 8
    for (int s = 0; s < CHUNK; s++) {
        uint4 u = src[(size_t)s * (HDIM / 4)];
        float a0, b0, a1, b1, a2, b2, a3, b3;
        unpack_ab(u.x, a0, b0); unpack_ab(u.y, a1, b1);
        unpack_ab(u.z, a2, b2); unpack_ab(u.w, a3, b3);
        h0 = fmaf(a0, h0, b0);
        h1 = fmaf(a1, h1, b1);
        h2 = fmaf(a2, h2, b2);
        h3 = fmaf(a3, h3, b3);
        dst[(size_t)s * (HDIM / 4)] = make_float4(h0, h1, h2, h3);
    }
}

// ---------------- launch ----------------
extern "C" void kernel_launch(void* const* d_in, const int* in_sizes, int n_in,
                              void* d_out, int out_size)
{
    const float* x  = (const float*)d_in[0];
    const float* h0 = (const float*)d_in[1];
    const float* Wz = (const float*)d_in[2];
    const float* bz = (const float*)d_in[3];
    const float* Wh = (const float*)d_in[4];
    const float* bh = (const float*)d_in[5];
    float* out = (float*)d_out;

    cudaFuncSetAttribute(gemm_gate_kernel,
                         cudaFuncAttributeMaxDynamicSharedMemorySize, DYN_SMEM);

    const int cvt_items = CVT_X8 + 2 * CVT_W8;   // 2.36M
    convert_kernel<<<cvt_items / 256, 256>>>(x, Wz, Wh);

    dim3 gGemm(HDIM / BN, M_TOTAL / BM);       // (8, 128)
    gemm_gate_kernel<<<gGemm, 256, DYN_SMEM>>>(bz, bh);

    dim3 gScan4(HDIM / 1024, NCHUNK, BS);      // 4 channels/thread
    scan_agg_kernel<<<gScan4, 256>>>();

    dim3 gCarry(HDIM / 64, BS);                // 64 CTAs x 64 threads
    scan_carry_kernel<<<gCarry, 64>>>(h0);

    scan_apply_kernel<<<gScan4, 256>>>(out);
}

// round 16
// speedup vs baseline: 1.0388x; 1.0388x over previous
#include <cuda_runtime.h>
#include <cuda_fp16.h>
#include <cstdint>

// ---------------- problem dims ----------------
#define BS    4
#define SEQ   4096
#define DIN   1024
#define HDIM  1024
#define M_TOTAL (BS*SEQ)       // 16384
#define NCHUNK 64
#define CHUNK  (SEQ/NCHUNK)    // 64

// ---------------- GEMM tiling ----------------
#define BM 128
#define BN 128
#define BK 64
#define KTILES (DIN/BK)        // 16
#define STAGES 4

#define TILE_BYTES (128*128)
#define STAGE_BYTES (3*TILE_BYTES)         // 48 KB
#define DYN_SMEM (STAGES*STAGE_BYTES)      // 192 KB

// ---------------- scratch ----------------
__device__ uint32_t g_AB[(size_t)M_TOTAL*HDIM]; // packed half2 (a, b)
__device__ float g_AggA[BS*NCHUNK*HDIM];
__device__ float g_AggB[BS*NCHUNK*HDIM];
__device__ float g_Carry[BS*NCHUNK*HDIM];
__device__ __half g_x16[(size_t)M_TOTAL*DIN];
__device__ __half g_wz16[HDIM*DIN];
__device__ __half g_wh16[HDIM*DIN];

// ---------------- helpers ----------------
__device__ __forceinline__ uint32_t smem_u32(const void* p) {
    uint32_t a;
    asm("{ .reg .u64 t; cvta.to.shared.u64 t, %1; cvt.u32.u64 %0, t; }"
        : "=r"(a) : "l"(p));
    return a;
}

__device__ __forceinline__ void cp_async16(uint32_t saddr, const void* gptr) {
    asm volatile("cp.async.cg.shared.global [%0], [%1], 16;"
                 :: "r"(saddr), "l"(gptr) : "memory");
}
#define CP_COMMIT() asm volatile("cp.async.commit_group;" ::: "memory")
#define CP_WAIT2()  asm volatile("cp.async.wait_group 2;" ::: "memory")

__device__ __forceinline__ void ldmatrix_x4(uint32_t* r, uint32_t addr) {
    asm volatile("ldmatrix.sync.aligned.m8n8.x4.shared.b16 {%0,%1,%2,%3}, [%4];"
                 : "=r"(r[0]), "=r"(r[1]), "=r"(r[2]), "=r"(r[3]) : "r"(addr));
}

__device__ __forceinline__ void mma_fp16(float* d, const uint32_t* a,
                                         uint32_t b0, uint32_t b1) {
    asm volatile(
        "mma.sync.aligned.m16n8k16.row.col.f32.f16.f16.f32 "
        "{%0,%1,%2,%3}, {%4,%5,%6,%7}, {%8,%9}, {%0,%1,%2,%3};"
        : "+f"(d[0]), "+f"(d[1]), "+f"(d[2]), "+f"(d[3])
        : "r"(a[0]), "r"(a[1]), "r"(a[2]), "r"(a[3]), "r"(b0), "r"(b1));
}

__device__ __forceinline__ float g_fn(float x) {
    return (x >= 0.0f) ? (x + 0.5f) : 1.0f / (1.0f + __expf(-x));
}

__device__ __forceinline__ uint32_t pack_ab(float a, float b) {
    __half2 h = __floats2half2_rn(a, b);
    return *(uint32_t*)&h;
}
__device__ __forceinline__ void unpack_ab(uint32_t u, float& a, float& b) {
    __half2 h = *(__half2*)&u;
    a = __low2float(h);
    b = __high2float(h);
}

// ---------------- fp32 -> fp16 convert (8 floats / thread) ----------------
#define CVT_X8  (M_TOTAL*DIN/8)
#define CVT_W8  (HDIM*DIN/8)
__global__ void convert_kernel(const float* __restrict__ x,
                               const float* __restrict__ Wz,
                               const float* __restrict__ Wh)
{
    const int i = blockIdx.x * blockDim.x + threadIdx.x;
    const float* src; __half* dst; int j;
    if (i < CVT_X8)                { src = x;  dst = g_x16;  j = i; }
    else if (i < CVT_X8 + CVT_W8)  { src = Wz; dst = g_wz16; j = i - CVT_X8; }
    else                           { src = Wh; dst = g_wh16; j = i - CVT_X8 - CVT_W8; }
    const float4* s = (const float4*)(src + (size_t)j * 8);
    float4 v0 = s[0], v1 = s[1];
    __half2 h0 = __floats2half2_rn(v0.x, v0.y);
    __half2 h1 = __floats2half2_rn(v0.z, v0.w);
    __half2 h2 = __floats2half2_rn(v1.x, v1.y);
    __half2 h3 = __floats2half2_rn(v1.z, v1.w);
    uint4 pk = make_uint4(*(uint32_t*)&h0, *(uint32_t*)&h1,
                          *(uint32_t*)&h2, *(uint32_t*)&h3);
    *(uint4*)(dst + (size_t)j * 8) = pk;
}

// ---------------- fused dual GEMM (fp16 mma) + gate epilogue ----------------
__global__ void __launch_bounds__(256, 1)
gemm_gate_kernel(const float* __restrict__ bz, const float* __restrict__ bh)
{
    extern __shared__ __align__(16) char dyn_smem[];
    __shared__ float sbz[BN], sbh[BN];

    const uint32_t dynb = smem_u32(dyn_smem);
    const int tid  = threadIdx.x;
    const int warp = tid >> 5;
    const int lane = tid & 31;
    const int n0 = blockIdx.x * BN;
    const int m0 = blockIdx.y * BM;

    const int wm = warp >> 2;
    const int wn = warp & 3;

    if (tid < BN) { sbz[tid] = bz[n0 + tid]; sbh[tid] = bh[n0 + tid]; }

    uint32_t stA[STAGES], stBz[STAGES], stBh[STAGES];
#pragma unroll
    for (int s = 0; s < STAGES; s++) {
        stA[s]  = dynb + s * STAGE_BYTES;
        stBz[s] = stA[s] + TILE_BYTES;
        stBh[s] = stBz[s] + TILE_BYTES;
    }

    auto load_stage = [&](int kt, int s) {
        const int kb = kt * BK;
#pragma unroll
        for (int i = 0; i < 4; i++) {
            int v = tid + i * 256, r = v >> 3, c = v & 7;
            uint32_t off = (uint32_t)(r * 128 + ((c ^ (r & 7)) << 4));
            cp_async16(stA[s] + off,  g_x16  + (size_t)(m0 + r) * DIN + kb + c * 8);
            cp_async16(stBz[s] + off, g_wz16 + (size_t)(n0 + r) * DIN + kb + c * 8);
            cp_async16(stBh[s] + off, g_wh16 + (size_t)(n0 + r) * DIN + kb + c * 8);
        }
    };

    float acc[2][4][4][4];
#pragma unroll
    for (int o = 0; o < 2; o++)
#pragma unroll
        for (int a = 0; a < 4; a++)
#pragma unroll
            for (int b = 0; b < 4; b++)
#pragma unroll
                for (int c = 0; c < 4; c++) acc[o][a][b][c] = 0.f;

    load_stage(0, 0); CP_COMMIT();
    load_stage(1, 1); CP_COMMIT();
    load_stage(2, 2); CP_COMMIT();

    const int lrow = lane & 15;
    const int lkh  = lane >> 4;

    uint32_t afrag[2][4][4];
    uint32_t bfZ[2][2][4];
    uint32_t bfH[2][2][4];

    for (int kt = 0; kt < KTILES; kt++) {
        CP_WAIT2();
        __syncthreads();
        if (kt + 3 < KTILES) load_stage(kt + 3, (kt + 3) % STAGES);
        CP_COMMIT();

        const int s = kt % STAGES;
        const uint32_t baseA = stA[s], baseZ = stBz[s], baseH = stBh[s];

        auto frag_load = [&](int ks, int buf) {
            const int ch = ks * 2 + lkh;
#pragma unroll
            for (int mf = 0; mf < 4; mf++) {
                const int row = wm * 64 + mf * 16 + lrow;
                ldmatrix_x4(afrag[buf][mf], baseA + row * 128 + ((ch ^ (row & 7)) << 4));
            }
#pragma unroll
            for (int g = 0; g < 2; g++) {
                const int row = wn * 32 + g * 16 + lrow;
                const uint32_t soff = row * 128 + ((ch ^ (row & 7)) << 4);
                ldmatrix_x4(bfZ[buf][g], baseZ + soff);
                ldmatrix_x4(bfH[buf][g], baseH + soff);
            }
        };

        frag_load(0, 0);
#pragma unroll
        for (int ks = 0; ks < 4; ks++) {
            const int cur = ks & 1;
            if (ks < 3) frag_load(ks + 1, cur ^ 1);
#pragma unroll
            for (int g = 0; g < 2; g++) {
#pragma unroll
                for (int mf = 0; mf < 4; mf++) {
                    mma_fp16(acc[0][mf][g * 2 + 0], afrag[cur][mf], bfZ[cur][g][0], bfZ[cur][g][2]);
                    mma_fp16(acc[0][mf][g * 2 + 1], afrag[cur][mf], bfZ[cur][g][1], bfZ[cur][g][3]);
                    mma_fp16(acc[1][mf][g * 2 + 0], afrag[cur][mf], bfH[cur][g][0], bfH[cur][g][2]);
                    mma_fp16(acc[1][mf][g * 2 + 1], afrag[cur][mf], bfH[cur][g][1], bfH[cur][g][3]);
                }
            }
        }
    }
    __syncthreads();

    // ---------- epilogue: gates + store packed (a,b) ----------
#pragma unroll
    for (int mf = 0; mf < 4; mf++) {
#pragma unroll
        for (int nf = 0; nf < 4; nf++) {
            const int nl = wn * 32 + nf * 8 + (lane & 3) * 2;
            const float bz0 = sbz[nl], bz1 = sbz[nl + 1];
            const float bh0 = sbh[nl], bh1 = sbh[nl + 1];
#pragma unroll
            for (int rr = 0; rr < 2; rr++) {
                const int m = m0 + wm * 64 + mf * 16 + (lane >> 2) + rr * 8;
                const float k0 = acc[0][mf][nf][rr * 2 + 0] + bz0;
                const float k1 = acc[0][mf][nf][rr * 2 + 1] + bz1;
                const float p0 = acc[1][mf][nf][rr * 2 + 0] + bh0;
                const float p1 = acc[1][mf][nf][rr * 2 + 1] + bh1;
                const float a0 = 1.0f / (1.0f + __expf(k0));
                const float a1 = 1.0f / (1.0f + __expf(k1));
                const float b0 = (1.0f - a0) * g_fn(p0);
                const float b1 = (1.0f - a1) * g_fn(p1);
                *(uint2*)&g_AB[(size_t)m * HDIM + n0 + nl] =
                    make_uint2(pack_ab(a0, b0), pack_ab(a1, b1));
            }
        }
    }
}

// ---------------- scan pass 1: per-chunk aggregates (2 channels/thread) ----------------
__global__ void scan_agg_kernel()
{
    const int h2 = blockIdx.x * blockDim.x + threadIdx.x;   // channel pair
    const int c = blockIdx.y;
    const int b = blockIdx.z;
    const uint2* src = (const uint2*)g_AB
                     + (size_t)(b * SEQ + c * CHUNK) * (HDIM / 2) + h2;

    float A0 = 1.0f, B0 = 0.0f, A1 = 1.0f, B1 = 0.0f;
#pragma unroll 8
    for (int s = 0; s < CHUNK; s++) {
        uint2 u = src[(size_t)s * (HDIM / 2)];
        float a0, b0, a1, b1;
        unpack_ab(u.x, a0, b0);
        unpack_ab(u.y, a1, b1);
        B0 = fmaf(a0, B0, b0); A0 *= a0;
        B1 = fmaf(a1, B1, b1); A1 *= a1;
    }
    const int o = (b * NCHUNK + c) * HDIM + 2 * h2;
    g_AggA[o]     = A0; g_AggB[o]     = B0;
    g_AggA[o + 1] = A1; g_AggB[o + 1] = B1;
}

// ---------------- scan pass 2: inter-chunk carry (64 CTAs x 64 thr) ----------------
__global__ void scan_carry_kernel(const float* __restrict__ h0in)
{
    const int h = blockIdx.x * blockDim.x + threadIdx.x;
    const int b = blockIdx.y;
    float carry = g_fn(h0in[b * HDIM + h]);

    const int base = b * NCHUNK * HDIM + h;

    float A[2][16], Bv[2][16];
#pragma unroll
    for (int j = 0; j < 16; j++) {
        A[0][j]  = g_AggA[base + j * HDIM];
        Bv[0][j] = g_AggB[base + j * HDIM];
    }

#pragma unroll
    for (int grp = 0; grp < 4; grp++) {
        const int cb = grp & 1;
        if (grp < 3) {
            const int nb = base + (grp + 1) * 16 * HDIM;
#pragma unroll
            for (int j = 0; j < 16; j++) {
                A[cb ^ 1][j]  = g_AggA[nb + j * HDIM];
                Bv[cb ^ 1][j] = g_AggB[nb + j * HDIM];
            }
        }
        const int ob = base + grp * 16 * HDIM;
#pragma unroll
        for (int j = 0; j < 16; j++) {
            g_Carry[ob + j * HDIM] = carry;
            carry = fmaf(A[cb][j], carry, Bv[cb][j]);
        }
    }
}

// ---------------- scan pass 3: apply + write output (2 channels/thread) ----------------
__global__ void scan_apply_kernel(float* __restrict__ out)
{
    const int h2 = blockIdx.x * blockDim.x + threadIdx.x;   // channel pair
    const int c = blockIdx.y;
    const int b = blockIdx.z;
    const uint2* src = (const uint2*)g_AB
                     + (size_t)(b * SEQ + c * CHUNK) * (HDIM / 2) + h2;
    float2* dst = (float2*)(out + (size_t)(b * SEQ + c * CHUNK) * HDIM) + h2;

    const int co = (b * NCHUNK + c) * HDIM + 2 * h2;
    float h0 = g_Carry[co];
    float h1 = g_Carry[co + 1];
#pragma unroll 8
    for (int s = 0; s < CHUNK; s++) {
        uint2 u = src[(size_t)s * (HDIM / 2)];
        float a0, b0, a1, b1;
        unpack_ab(u.x, a0, b0);
        unpack_ab(u.y, a1, b1);
        h0 = fmaf(a0, h0, b0);
        h1 = fmaf(a1, h1, b1);
        dst[(size_t)s * (HDIM / 2)] = make_float2(h0, h1);
    }
}

// ---------------- launch ----------------
extern "C" void kernel_launch(void* const* d_in, const int* in_sizes, int n_in,
                              void* d_out, int out_size)
{
    const float* x  = (const float*)d_in[0];
    const float* h0 = (const float*)d_in[1];
    const float* Wz = (const float*)d_in[2];
    const float* bz = (const float*)d_in[3];
    const float* Wh = (const float*)d_in[4];
    const float* bh = (const float*)d_in[5];
    float* out = (float*)d_out;

    cudaFuncSetAttribute(gemm_gate_kernel,
                         cudaFuncAttributeMaxDynamicSharedMemorySize, DYN_SMEM);

    const int cvt_items = CVT_X8 + 2 * CVT_W8;   // 2.36M
    convert_kernel<<<cvt_items / 256, 256>>>(x, Wz, Wh);

    dim3 gGemm(HDIM / BN, M_TOTAL / BM);       // (8, 128)
    gemm_gate_kernel<<<gGemm, 256, DYN_SMEM>>>(bz, bh);

    dim3 gScan2(HDIM / 512, NCHUNK, BS);       // 2 channels/thread
    scan_agg_kernel<<<gScan2, 256>>>();

    dim3 gCarry(HDIM / 64, BS);                // 64 CTAs x 64 threads
    scan_carry_kernel<<<gCarry, 64>>>(h0);

    scan_apply_kernel<<<gScan2, 256>>>(out);
}